// round 11
// baseline (speedup 1.0000x reference)
#include <cuda_runtime.h>
#include <math_constants.h>

#define BB 2
#define NN 2048
#define MM 512
#define GG 27
#define CAGG 32
#define CPOST 128
#define GC (GG*CAGG)      // 864
#define BM (BB*MM)        // 1024
#define NCENT (BM*GG)     // 27648
#define NCELL 512         // 8^3 grid
#define HCELL 1.25f
#define INVH 0.8f
#define KSPLIT 9

// Scratch (device globals; allocation is forbidden)
__device__ __align__(16) float4 g_pts4[BB][NN];          // binned points
__device__ int   g_cstart[BB][NCELL+1];
__device__ int   g_perm[BB][NN];
__device__ __align__(16) float g_feats[BB*NN*32];        // binned reduced feats
__device__ __align__(16) float g_wT[GG*41*CAGG];         // weights [g][i][o]
__device__ __align__(16) float g_sc1[GC], g_sh1[GC];     // folded BN1
__device__ __align__(16) float g_x[BM*GC];               // grouped-conv out
__device__ __align__(16) float g_part[KSPLIT][BM*CPOST]; // split-K partials

// ---------------------------------------------------------------------------
// K_wt: transpose grouped weights to [g][i][o]; fold BN1 into scale/shift
// ---------------------------------------------------------------------------
__global__ void k_wt(const float* __restrict__ wg, const float* __restrict__ g1,
                     const float* __restrict__ b1, const float* __restrict__ mu1,
                     const float* __restrict__ v1) {
    int t = blockIdx.x * 256 + threadIdx.x;
    if (t < GG*41*CAGG) {
        int g = t / (41*CAGG);
        int rm = t - g*(41*CAGG);
        int i = rm >> 5, o = rm & 31;
        g_wT[t] = wg[g*(CAGG*41) + o*41 + i];
    }
    if (t < GC) {
        float sc = g1[t] * rsqrtf(v1[t] + 1e-5f);
        g_sc1[t] = sc;
        g_sh1[t] = b1[t] - mu1[t]*sc;
    }
}

// ---------------------------------------------------------------------------
// K_bin: per-batch counting sort of support points into 8^3 cells
// ---------------------------------------------------------------------------
__global__ __launch_bounds__(256) void k_bin(const float* __restrict__ sxyz) {
    __shared__ int cnt[NCELL];
    __shared__ int start[NCELL+1];
    const int b = blockIdx.x;
    const int tid = threadIdx.x;
    for (int c = tid; c < NCELL; c += 256) cnt[c] = 0;
    __syncthreads();
    for (int p = tid; p < NN; p += 256) {
        const float* s = sxyz + (b*NN + p)*3;
        int cx = min(max((int)floorf(s[0]*INVH), 0), 7);
        int cy = min(max((int)floorf(s[1]*INVH), 0), 7);
        int cz = min(max((int)floorf(s[2]*INVH), 0), 7);
        atomicAdd(&cnt[(cx*8+cy)*8+cz], 1);
    }
    __syncthreads();
    if (tid < 32) {
        int base = tid*16, s = 0;
        #pragma unroll
        for (int i = 0; i < 16; ++i) s += cnt[base+i];
        int inc = s;
        #pragma unroll
        for (int o = 1; o < 32; o <<= 1) {
            int v = __shfl_up_sync(0xffffffffu, inc, o);
            if (tid >= o) inc += v;
        }
        int run = inc - s;
        #pragma unroll
        for (int i = 0; i < 16; ++i) { start[base+i] = run; run += cnt[base+i]; }
        if (tid == 31) start[NCELL] = run;
    }
    __syncthreads();
    for (int c = tid; c < NCELL; c += 256) cnt[c] = start[c];
    __syncthreads();
    for (int p = tid; p < NN; p += 256) {
        const float* s = sxyz + (b*NN + p)*3;
        float x = s[0], y = s[1], z = s[2];
        int cx = min(max((int)floorf(x*INVH), 0), 7);
        int cy = min(max((int)floorf(y*INVH), 0), 7);
        int cz = min(max((int)floorf(z*INVH), 0), 7);
        int pos = atomicAdd(&cnt[(cx*8+cy)*8+cz], 1);
        g_pts4[b][pos] = make_float4(x, y, z, 0.0f);
        g_perm[b][pos] = p;
    }
    for (int c = tid; c <= NCELL; c += 256) g_cstart[b][c] = start[c];
}

// ---------------------------------------------------------------------------
// K_reduce: channel reduction 128->32 gathered into binned order
// ---------------------------------------------------------------------------
__global__ void k_reduce(const float* __restrict__ sf) {
    int t = blockIdx.x * 256 + threadIdx.x;
    if (t >= BB*NN*32) return;
    int row = t >> 5, c = t & 31;
    int b = row / NN, p = row - b*NN;
    int orig = g_perm[b][p];
    const float* q = sf + (b*NN + orig)*128 + c;
    g_feats[t] = q[0] + q[32] + q[64] + q[96];
}

// Branchless insert of (d,i) into sorted triple d0<=d1<=d2
__device__ __forceinline__ void ins3(float d, int i,
        float& d0, int& i0, float& d1, int& i1, float& d2, int& i2) {
    bool c2 = d < d2, c1 = d < d1, c0 = d < d0;
    d2 = c1 ? d1 : (c2 ? d : d2);  i2 = c1 ? i1 : (c2 ? i : i2);
    d1 = c0 ? d0 : (c1 ? d : d1);  i1 = c0 ? i0 : (c1 ? i : i1);
    d0 = c0 ? d  : d0;             i0 = c0 ? i  : i0;
}

// ---------------------------------------------------------------------------
// K_nn: ONE WARP PER CENTER (fully convergent). Box-growing z-run scan,
// count-based termination, top-3 via 3 global-min pops, interp + fused
// grouped conv + BN1 + ReLU. block 256 = 8 warps; grid NCENT/8.
// ---------------------------------------------------------------------------
__global__ __launch_bounds__(256) void k_nn(const float* __restrict__ nxyz) {
    __shared__ __align__(16) float sv[8][48];   // staged vec[41] per warp
    __shared__ int cst[NCELL+1];
    const int tid  = threadIdx.x;
    const int warp = tid >> 5;
    const int l    = tid & 31;
    const int cid  = blockIdx.x*8 + warp;
    const int b    = (blockIdx.x*8) / (MM*GG);   // 13824/8: never straddles

    for (int i = tid; i < NCELL+1; i += 256) cst[i] = g_cstart[b][i];
    __syncthreads();

    const int m = cid / GG, g = cid - m*GG;
    const int ixg = g / 9;
    const int iyg = (g - ixg*9) / 3;
    const int izg = g - ixg*9 - iyg*3;
    const float cx = nxyz[m*3+0] + __fadd_rn(__fmul_rn((float)ixg + 0.5f, 1.6f), -2.4f);
    const float cy = nxyz[m*3+1] + __fadd_rn(__fmul_rn((float)iyg + 0.5f, 1.6f), -2.4f);
    const float cz = nxyz[m*3+2] + __fadd_rn(__fmul_rn((float)izg + 0.5f, 1.6f), -2.4f);
    const int icx = (int)floorf(cx * INVH);
    const int icy = (int)floorf(cy * INVH);
    const int icz = (int)floorf(cz * INVH);

    const float INF = CUDART_INF_F;
    float d0 = INF, d1 = INF, d2v = INF;   // per-lane triple (disjoint sets)
    int   i0 = -1,  i1 = -1,  i2 = -1;

    const float4* __restrict__ pts = g_pts4[b];

    // box-growing scan; prev box tracked for ring = newbox \ prevbox
    int xlo = 1, xhi = 0, ylo = 1, yhi = 0, zlo = 1, zhi = 0;  // empty
    bool havePrev = false;

    for (int r = 1; r <= 10; ++r) {
        const int nxlo = max(icx-r, 0), nxhi = min(icx+r, 7);
        const int nylo = max(icy-r, 0), nyhi = min(icy+r, 7);
        const int nzlo = max(icz-r, 0), nzhi = min(icz+r, 7);
        const bool valid = (nxhi >= nxlo) && (nyhi >= nylo) && (nzhi >= nzlo);
        if (valid) {
            for (int x = nxlo; x <= nxhi; ++x)
            for (int y = nylo; y <= nyhi; ++y) {
                const int base = (x*8 + y)*8;
                const bool rowPrev = havePrev &&
                    x >= xlo && x <= xhi && y >= ylo && y <= yhi;
                int al, ah, bl, bh;
                if (rowPrev) { al = nzlo; ah = zlo-1; bl = zhi+1; bh = nzhi; }
                else         { al = nzlo; ah = nzhi;  bl = 1;     bh = 0;   }
                if (ah >= al) {
                    const int s = cst[base+al], e = cst[base+ah+1];
                    for (int j = s + l; j < e; j += 32) {
                        float4 p = __ldg(&pts[j]);
                        float dx = cx - p.x, dy = cy - p.y, dz = cz - p.z;
                        float dsq = fmaf(dx, dx, fmaf(dy, dy, dz*dz));
                        float ch  = fmaxf(fabsf(dx), fmaxf(fabsf(dy), fabsf(dz)));
                        float dd  = (ch <= 4.8f) ? dsq : INF;
                        ins3(dd, j, d0, i0, d1, i1, d2v, i2);
                    }
                }
                if (bh >= bl) {
                    const int s = cst[base+bl], e = cst[base+bh+1];
                    for (int j = s + l; j < e; j += 32) {
                        float4 p = __ldg(&pts[j]);
                        float dx = cx - p.x, dy = cy - p.y, dz = cz - p.z;
                        float dsq = fmaf(dx, dx, fmaf(dy, dy, dz*dz));
                        float ch  = fmaxf(fabsf(dx), fmaxf(fabsf(dy), fabsf(dz)));
                        float dd  = (ch <= 4.8f) ? dsq : INF;
                        ins3(dd, j, d0, i0, d1, i1, d2v, i2);
                    }
                }
            }
            xlo = nxlo; xhi = nxhi; ylo = nylo; yhi = nyhi; zlo = nzlo; zhi = nzhi;
            havePrev = true;

            // termination: distance from c to nearest UNSCANNED slab
            float bound = INF;
            if (xlo > 0) bound = fminf(bound, cx - (float)xlo*HCELL);
            if (xhi < 7) bound = fminf(bound, (float)(xhi+1)*HCELL - cx);
            if (ylo > 0) bound = fminf(bound, cy - (float)ylo*HCELL);
            if (yhi < 7) bound = fminf(bound, (float)(yhi+1)*HCELL - cy);
            if (zlo > 0) bound = fminf(bound, cz - (float)zlo*HCELL);
            if (zhi < 7) bound = fminf(bound, (float)(zhi+1)*HCELL - cz);
            if (bound == INF) break;          // whole grid scanned
            bound -= 1e-3f;                   // fp cell-assignment margin
            if (bound > 0.0f) {
                float b2 = bound * bound;
                unsigned cnt = (unsigned)(d0 < b2) + (unsigned)(d1 < b2)
                             + (unsigned)(d2v < b2);
                if (__reduce_add_sync(0xffffffffu, cnt) >= 3) break;
            }
        }
    }

    // top-3 via 3 successive global-min pops (positive floats order as u32)
    float td[3]; int ti[3];
    #pragma unroll
    for (int k = 0; k < 3; ++k) {
        unsigned kbits = __reduce_min_sync(0xffffffffu, __float_as_uint(d0));
        unsigned ball  = __ballot_sync(0xffffffffu, __float_as_uint(d0) == kbits);
        int src = __ffs(ball) - 1;
        td[k] = __uint_as_float(kbits);
        ti[k] = __shfl_sync(0xffffffffu, i0, src);
        if (l == src) { d0 = d1; i0 = i1; d1 = d2v; i1 = i2; d2v = INF; i2 = -1; }
    }

    const bool empty = !(td[0] < INF);
    float r0 = (td[0] < INF) ? 1.0f/(td[0] + 1e-8f) : 0.0f;
    float r1 = (td[1] < INF) ? 1.0f/(td[1] + 1e-8f) : 0.0f;
    float r2 = (td[2] < INF) ? 1.0f/(td[2] + 1e-8f) : 0.0f;
    float ssum = fmaxf(r0 + r1 + r2, 1e-8f);
    float w0 = r0/ssum, w1 = r1/ssum, w2 = r2/ssum;
    int ti0 = ti[0] < 0 ? 0 : ti[0];
    int ti1 = ti[1] < 0 ? ti0 : ti[1];
    int ti2 = ti[2] < 0 ? ti0 : ti[2];

    // interp: lane handles 1 feature channel -> stage to smem
    {
        const float* F0 = g_feats + (b*NN + ti0)*32;
        const float* F1 = g_feats + (b*NN + ti1)*32;
        const float* F2 = g_feats + (b*NN + ti2)*32;
        float f = w0*__ldg(&F0[l]) + w1*__ldg(&F1[l]) + w2*__ldg(&F2[l]);
        sv[warp][l] = empty ? 0.0f : f;
        if (l < 9) {
            int k = l / 3, j = l - (l/3)*3;
            int isel = (k == 0) ? ti0 : ((k == 1) ? ti1 : ti2);
            float4 p = __ldg(&pts[isel]);
            float cj = (j == 0) ? cx : ((j == 1) ? cy : cz);
            float pj = (j == 0) ? p.x : ((j == 1) ? p.y : p.z);
            sv[warp][32 + l] = empty ? 0.0f : (cj - pj);
        }
    }
    __syncwarp();

    // fused grouped conv: lane computes output channel l
    const float* wcol = g_wT + g*(41*CAGG) + l;
    float acc = 0.0f;
    #pragma unroll
    for (int i = 0; i < 41; ++i)
        acc = fmaf(sv[warp][i], __ldg(&wcol[i*CAGG]), acc);
    const int gc = g*CAGG + l;
    g_x[m*GC + gc] = fmaxf(fmaf(acc, __ldg(&g_sc1[gc]), __ldg(&g_sh1[gc])), 0.0f);
}

// ---------------------------------------------------------------------------
// K_post: split-K GEMM partials. CTA tile 64m x 128n, k=96 per split.
// ---------------------------------------------------------------------------
__global__ __launch_bounds__(128) void k_post(const float* __restrict__ wp) {
    __shared__ float sA[32][68];
    __shared__ float sB[32][132];
    const int tid = threadIdx.x;
    const int tx = tid & 15;
    const int ty = tid >> 4;
    const int m0 = blockIdx.x * 64;
    const int kb0 = blockIdx.y * 96;

    float acc[8][8];
    #pragma unroll
    for (int i = 0; i < 8; ++i)
        #pragma unroll
        for (int j = 0; j < 8; ++j) acc[i][j] = 0.0f;

    for (int kc = 0; kc < 96; kc += 32) {
        const int kb = kb0 + kc;
        #pragma unroll
        for (int i = 0; i < 4; ++i) {               // A: 64m x 32k
            int f = tid + i*128;
            int mm = f >> 3, kq = (f & 7) << 2;
            float4 vv = *(const float4*)(g_x + (m0+mm)*GC + kb + kq);
            sA[kq+0][mm] = vv.x; sA[kq+1][mm] = vv.y;
            sA[kq+2][mm] = vv.z; sA[kq+3][mm] = vv.w;
        }
        #pragma unroll
        for (int i = 0; i < 8; ++i) {               // B: 128n x 32k
            int f = tid + i*128;
            int nr = f >> 3, kq = (f & 7) << 2;
            float4 vv = *(const float4*)(wp + nr*GC + kb + kq);
            sB[kq+0][nr] = vv.x; sB[kq+1][nr] = vv.y;
            sB[kq+2][nr] = vv.z; sB[kq+3][nr] = vv.w;
        }
        __syncthreads();
        #pragma unroll
        for (int k = 0; k < 32; ++k) {
            float av[8], bv[8];
            *(float4*)&av[0] = *(const float4*)&sA[k][ty*8];
            *(float4*)&av[4] = *(const float4*)&sA[k][ty*8 + 4];
            *(float4*)&bv[0] = *(const float4*)&sB[k][tx*4];
            *(float4*)&bv[4] = *(const float4*)&sB[k][64 + tx*4];
            #pragma unroll
            for (int i = 0; i < 8; ++i)
                #pragma unroll
                for (int j = 0; j < 8; ++j)
                    acc[i][j] = fmaf(av[i], bv[j], acc[i][j]);
        }
        __syncthreads();
    }

    float* dst = g_part[blockIdx.y];
    #pragma unroll
    for (int i = 0; i < 8; ++i) {
        int mrow = m0 + ty*8 + i;
        *(float4*)(dst + mrow*CPOST + tx*4)      = *(float4*)&acc[i][0];
        *(float4*)(dst + mrow*CPOST + 64 + tx*4) = *(float4*)&acc[i][4];
    }
}

// ---------------------------------------------------------------------------
// K_fin: sum split-K partials + BN2 + ReLU
// ---------------------------------------------------------------------------
__global__ void k_fin(const float* __restrict__ g2, const float* __restrict__ b2,
                      const float* __restrict__ mu2, const float* __restrict__ v2,
                      float* __restrict__ out) {
    int t = blockIdx.x * 256 + threadIdx.x;
    if (t >= BM*CPOST) return;
    int c = t & 127;
    float s = 0.0f;
    #pragma unroll
    for (int k = 0; k < KSPLIT; ++k) s += g_part[k][t];
    float scale = g2[c] * rsqrtf(v2[c] + 1e-5f);
    float shift = b2[c] - mu2[c]*scale;
    out[t] = fmaxf(fmaf(s, scale, shift), 0.0f);
}

// ---------------------------------------------------------------------------
extern "C" void kernel_launch(void* const* d_in, const int* in_sizes, int n_in,
                              void* d_out, int out_size) {
    const float* sxyz  = (const float*)d_in[0];
    const float* sfeat = (const float*)d_in[1];
    const float* nxyz  = (const float*)d_in[2];
    const float* wg    = (const float*)d_in[3];
    const float* g1    = (const float*)d_in[4];
    const float* b1    = (const float*)d_in[5];
    const float* m1    = (const float*)d_in[6];
    const float* v1    = (const float*)d_in[7];
    const float* wp    = (const float*)d_in[8];
    const float* g2    = (const float*)d_in[9];
    const float* b2    = (const float*)d_in[10];
    const float* m2    = (const float*)d_in[11];
    const float* v2    = (const float*)d_in[12];
    float* out = (float*)d_out;

    k_wt<<<(GG*41*CAGG + 255)/256, 256>>>(wg, g1, b1, m1, v1);
    k_bin<<<BB, 256>>>(sxyz);
    k_reduce<<<(BB*NN*32 + 255)/256, 256>>>(sfeat);
    k_nn<<<NCENT/8, 256>>>(nxyz);
    k_post<<<dim3(BM/64, KSPLIT), 128>>>(wp);
    k_fin<<<(BM*CPOST + 255)/256, 256>>>(g2, b2, m2, v2, out);
}

// round 12
// speedup vs baseline: 1.0815x; 1.0815x over previous
#include <cuda_runtime.h>
#include <math_constants.h>

#define BB 2
#define NN 2048
#define MM 512
#define GG 27
#define CAGG 32
#define CPOST 128
#define GC (GG*CAGG)      // 864
#define BM (BB*MM)        // 1024
#define NCENT (BM*GG)     // 27648
#define NCELL 512         // 8^3 grid
#define HCELL 1.25f
#define INVH 0.8f
#define KSPLIT 9

// Scratch (device globals; allocation is forbidden)
__device__ __align__(16) float4 g_pts4[BB][NN];          // binned points
__device__ int   g_cstart[BB][NCELL+1];
__device__ int   g_perm[BB][NN];
__device__ __align__(16) float g_feats[BB*NN*32];        // binned reduced feats
__device__ __align__(16) float g_wT[GG*41*CAGG];         // weights [g][i][o]
__device__ __align__(16) float g_sc1[GC], g_sh1[GC];     // folded BN1
__device__ __align__(16) float g_x[BM*GC];               // grouped-conv out
__device__ __align__(16) float g_part[KSPLIT][BM*CPOST]; // split-K partials

// ---------------------------------------------------------------------------
// K_wt: transpose grouped weights to [g][i][o]; fold BN1 into scale/shift
// ---------------------------------------------------------------------------
__global__ void k_wt(const float* __restrict__ wg, const float* __restrict__ g1,
                     const float* __restrict__ b1, const float* __restrict__ mu1,
                     const float* __restrict__ v1) {
    int t = blockIdx.x * 256 + threadIdx.x;
    if (t < GG*41*CAGG) {
        int g = t / (41*CAGG);
        int rm = t - g*(41*CAGG);
        int i = rm >> 5, o = rm & 31;
        g_wT[t] = wg[g*(CAGG*41) + o*41 + i];
    }
    if (t < GC) {
        float sc = g1[t] * rsqrtf(v1[t] + 1e-5f);
        g_sc1[t] = sc;
        g_sh1[t] = b1[t] - mu1[t]*sc;
    }
}

// ---------------------------------------------------------------------------
// K_bin: per-batch counting sort of support points into 8^3 cells
// ---------------------------------------------------------------------------
__global__ __launch_bounds__(256) void k_bin(const float* __restrict__ sxyz) {
    __shared__ int cnt[NCELL];
    __shared__ int start[NCELL+1];
    const int b = blockIdx.x;
    const int tid = threadIdx.x;
    for (int c = tid; c < NCELL; c += 256) cnt[c] = 0;
    __syncthreads();
    for (int p = tid; p < NN; p += 256) {
        const float* s = sxyz + (b*NN + p)*3;
        int cx = min(max((int)floorf(s[0]*INVH), 0), 7);
        int cy = min(max((int)floorf(s[1]*INVH), 0), 7);
        int cz = min(max((int)floorf(s[2]*INVH), 0), 7);
        atomicAdd(&cnt[(cx*8+cy)*8+cz], 1);
    }
    __syncthreads();
    if (tid < 32) {
        int base = tid*16, s = 0;
        #pragma unroll
        for (int i = 0; i < 16; ++i) s += cnt[base+i];
        int inc = s;
        #pragma unroll
        for (int o = 1; o < 32; o <<= 1) {
            int v = __shfl_up_sync(0xffffffffu, inc, o);
            if (tid >= o) inc += v;
        }
        int run = inc - s;
        #pragma unroll
        for (int i = 0; i < 16; ++i) { start[base+i] = run; run += cnt[base+i]; }
        if (tid == 31) start[NCELL] = run;
    }
    __syncthreads();
    for (int c = tid; c < NCELL; c += 256) cnt[c] = start[c];
    __syncthreads();
    for (int p = tid; p < NN; p += 256) {
        const float* s = sxyz + (b*NN + p)*3;
        float x = s[0], y = s[1], z = s[2];
        int cx = min(max((int)floorf(x*INVH), 0), 7);
        int cy = min(max((int)floorf(y*INVH), 0), 7);
        int cz = min(max((int)floorf(z*INVH), 0), 7);
        int pos = atomicAdd(&cnt[(cx*8+cy)*8+cz], 1);
        g_pts4[b][pos] = make_float4(x, y, z, 0.0f);
        g_perm[b][pos] = p;
    }
    for (int c = tid; c <= NCELL; c += 256) g_cstart[b][c] = start[c];
}

// ---------------------------------------------------------------------------
// K_reduce: channel reduction 128->32 gathered into binned order
// ---------------------------------------------------------------------------
__global__ void k_reduce(const float* __restrict__ sf) {
    int t = blockIdx.x * 256 + threadIdx.x;
    if (t >= BB*NN*32) return;
    int row = t >> 5, c = t & 31;
    int b = row / NN, p = row - b*NN;
    int orig = g_perm[b][p];
    const float* q = sf + (b*NN + orig)*128 + c;
    g_feats[t] = q[0] + q[32] + q[64] + q[96];
}

// Branchless insert of (d,i) into sorted triple d0<=d1<=d2
__device__ __forceinline__ void ins3(float d, int i,
        float& d0, int& i0, float& d1, int& i1, float& d2, int& i2) {
    bool c2 = d < d2, c1 = d < d1, c0 = d < d0;
    d2 = c1 ? d1 : (c2 ? d : d2);  i2 = c1 ? i1 : (c2 ? i : i2);
    d1 = c0 ? d0 : (c1 ? d : d1);  i1 = c0 ? i0 : (c1 ? i : i1);
    d0 = c0 ? d  : d0;             i0 = c0 ? i  : i0;
}

// ---------------------------------------------------------------------------
// K_nn: grid 3-NN per center (16-lane groups, 2 centers/warp) + interp +
// FUSED grouped conv + BN1 + ReLU. cid = g*BM + m -> block-uniform g:
// weights+BN staged in smem. Top-3 by 3 global-min pops. Writes g_x.
// block 256 = 16 groups; grid NCENT/16.
// ---------------------------------------------------------------------------
__global__ __launch_bounds__(256) void k_nn(const float* __restrict__ nxyz) {
    __shared__ __align__(16) float sv[16][48];   // staged vec[41] per group
    __shared__ __align__(16) float sw[41*CAGG];  // this block's g weights [i][o]
    __shared__ float ssc[CAGG], ssh[CAGG];
    __shared__ int cst[NCELL+1];
    const int tid = threadIdx.x;
    const int grp = tid >> 4;
    const int l   = tid & 15;
    const unsigned gmask = 0xffffu << (tid & 16);   // group-local mask
    const int cid = blockIdx.x*16 + grp;
    const int g   = cid / BM;                    // uniform within block
    const int m   = cid - g*BM;
    const int b   = ((blockIdx.x*16) % BM) / MM; // uniform (512%16==0)

    for (int i = tid; i < NCELL+1; i += 256) cst[i] = g_cstart[b][i];
    {
        const float* wsrc = g_wT + g*(41*CAGG);
        for (int i = tid; i < 41*CAGG; i += 256) sw[i] = wsrc[i];
        if (tid < CAGG) {
            ssc[tid] = g_sc1[g*CAGG + tid];
            ssh[tid] = g_sh1[g*CAGG + tid];
        }
    }
    __syncthreads();

    const int ixg = g / 9;
    const int iyg = (g - ixg*9) / 3;
    const int izg = g - ixg*9 - iyg*3;
    const float cx = nxyz[m*3+0] + __fadd_rn(__fmul_rn((float)ixg + 0.5f, 1.6f), -2.4f);
    const float cy = nxyz[m*3+1] + __fadd_rn(__fmul_rn((float)iyg + 0.5f, 1.6f), -2.4f);
    const float cz = nxyz[m*3+2] + __fadd_rn(__fmul_rn((float)izg + 0.5f, 1.6f), -2.4f);
    const int icx = (int)floorf(cx * INVH);
    const int icy = (int)floorf(cy * INVH);
    const int icz = (int)floorf(cz * INVH);

    const float INF = CUDART_INF_F;
    float d0 = INF, d1 = INF, d2v = INF;   // per-lane triple (disjoint sets)
    int   i0 = -1,  i1 = -1,  i2 = -1;

    const float4* __restrict__ pts = g_pts4[b];

    // box-growing scan; prev box tracked for ring = newbox \ prevbox
    int xlo = 1, xhi = 0, ylo = 1, yhi = 0, zlo = 1, zhi = 0;  // empty
    bool havePrev = false;

    for (int r = 1; r <= 10; ++r) {
        const int nxlo = max(icx-r, 0), nxhi = min(icx+r, 7);
        const int nylo = max(icy-r, 0), nyhi = min(icy+r, 7);
        const int nzlo = max(icz-r, 0), nzhi = min(icz+r, 7);
        const bool valid = (nxhi >= nxlo) && (nyhi >= nylo) && (nzhi >= nzlo);
        if (valid) {
            for (int x = nxlo; x <= nxhi; ++x)
            for (int y = nylo; y <= nyhi; ++y) {
                const int base = (x*8 + y)*8;
                const bool rowPrev = havePrev &&
                    x >= xlo && x <= xhi && y >= ylo && y <= yhi;
                int al, ah, bl, bh;
                if (rowPrev) { al = nzlo; ah = zlo-1; bl = zhi+1; bh = nzhi; }
                else         { al = nzlo; ah = nzhi;  bl = 1;     bh = 0;   }
                if (ah >= al) {
                    const int s = cst[base+al], e = cst[base+ah+1];
                    for (int j = s + l; j < e; j += 16) {
                        float4 p = __ldg(&pts[j]);
                        float dx = cx - p.x, dy = cy - p.y, dz = cz - p.z;
                        float dsq = fmaf(dx, dx, fmaf(dy, dy, dz*dz));
                        float ch  = fmaxf(fabsf(dx), fmaxf(fabsf(dy), fabsf(dz)));
                        float dd  = (ch <= 4.8f) ? dsq : INF;
                        ins3(dd, j, d0, i0, d1, i1, d2v, i2);
                    }
                }
                if (bh >= bl) {
                    const int s = cst[base+bl], e = cst[base+bh+1];
                    for (int j = s + l; j < e; j += 16) {
                        float4 p = __ldg(&pts[j]);
                        float dx = cx - p.x, dy = cy - p.y, dz = cz - p.z;
                        float dsq = fmaf(dx, dx, fmaf(dy, dy, dz*dz));
                        float ch  = fmaxf(fabsf(dx), fmaxf(fabsf(dy), fabsf(dz)));
                        float dd  = (ch <= 4.8f) ? dsq : INF;
                        ins3(dd, j, d0, i0, d1, i1, d2v, i2);
                    }
                }
            }
            xlo = nxlo; xhi = nxhi; ylo = nylo; yhi = nyhi; zlo = nzlo; zhi = nzhi;
            havePrev = true;

            // termination: distance from c to nearest UNSCANNED slab
            float bound = INF;
            if (xlo > 0) bound = fminf(bound, cx - (float)xlo*HCELL);
            if (xhi < 7) bound = fminf(bound, (float)(xhi+1)*HCELL - cx);
            if (ylo > 0) bound = fminf(bound, cy - (float)ylo*HCELL);
            if (yhi < 7) bound = fminf(bound, (float)(yhi+1)*HCELL - cy);
            if (zlo > 0) bound = fminf(bound, cz - (float)zlo*HCELL);
            if (zhi < 7) bound = fminf(bound, (float)(zhi+1)*HCELL - cz);
            if (bound == INF) break;          // whole grid scanned
            bound -= 1e-3f;                   // fp cell-assignment margin
            if (bound > 0.0f) {
                float b2 = bound * bound;
                unsigned cnt = (unsigned)(d0 < b2) + (unsigned)(d1 < b2)
                             + (unsigned)(d2v < b2);
                if (__reduce_add_sync(gmask, cnt) >= 3) break;
            }
        }
    }

    // top-3 via 3 successive group-min pops (positive floats order as u32)
    float td[3]; int ti[3];
    #pragma unroll
    for (int k = 0; k < 3; ++k) {
        unsigned kbits = __reduce_min_sync(gmask, __float_as_uint(d0));
        unsigned ball  = __ballot_sync(gmask, __float_as_uint(d0) == kbits);
        int src = __ffs(ball) - 1;                      // absolute lane id
        td[k] = __uint_as_float(kbits);
        ti[k] = __shfl_sync(gmask, i0, src);
        if ((tid & 31) == src) { d0 = d1; i0 = i1; d1 = d2v; i1 = i2; d2v = INF; i2 = -1; }
    }

    const bool empty = !(td[0] < INF);
    float r0 = (td[0] < INF) ? 1.0f/(td[0] + 1e-8f) : 0.0f;
    float r1 = (td[1] < INF) ? 1.0f/(td[1] + 1e-8f) : 0.0f;
    float r2 = (td[2] < INF) ? 1.0f/(td[2] + 1e-8f) : 0.0f;
    float ssum = fmaxf(r0 + r1 + r2, 1e-8f);
    float w0 = r0/ssum, w1 = r1/ssum, w2 = r2/ssum;
    int ti0 = ti[0] < 0 ? 0 : ti[0];
    int ti1 = ti[1] < 0 ? ti0 : ti[1];
    int ti2 = ti[2] < 0 ? ti0 : ti[2];

    // interp: lane handles 2 feature channels (float2) -> stage to smem
    {
        const float2* F0 = (const float2*)(g_feats + (b*NN + ti0)*32);
        const float2* F1 = (const float2*)(g_feats + (b*NN + ti1)*32);
        const float2* F2 = (const float2*)(g_feats + (b*NN + ti2)*32);
        float2 a = __ldg(&F0[l]), u = __ldg(&F1[l]), v = __ldg(&F2[l]);
        float2 f;
        f.x = empty ? 0.0f : (w0*a.x + w1*u.x + w2*v.x);
        f.y = empty ? 0.0f : (w0*a.y + w1*u.y + w2*v.y);
        ((float2*)sv[grp])[l] = f;
        if (l < 3) {
            int isel = (l == 0) ? ti0 : ((l == 1) ? ti1 : ti2);
            float4 p = __ldg(&pts[isel]);
            sv[grp][32 + l*3 + 0] = empty ? 0.0f : (cx - p.x);
            sv[grp][32 + l*3 + 1] = empty ? 0.0f : (cy - p.y);
            sv[grp][32 + l*3 + 2] = empty ? 0.0f : (cz - p.z);
        }
    }
    __syncwarp();

    // fused grouped conv from smem weights: lane computes channels 2l, 2l+1
    float a0 = 0.0f, a1 = 0.0f;
    #pragma unroll
    for (int i = 0; i < 41; ++i) {
        float vi = sv[grp][i];
        float2 w = *(const float2*)&sw[i*CAGG + 2*l];
        a0 = fmaf(vi, w.x, a0);
        a1 = fmaf(vi, w.y, a1);
    }
    float2 r;
    r.x = fmaxf(fmaf(a0, ssc[2*l],   ssh[2*l]),   0.0f);
    r.y = fmaxf(fmaf(a1, ssc[2*l+1], ssh[2*l+1]), 0.0f);
    *(float2*)(g_x + m*GC + g*CAGG + 2*l) = r;
}

// ---------------------------------------------------------------------------
// K_post: split-K GEMM partials. CTA tile 64m x 128n, k=96 per split.
// ---------------------------------------------------------------------------
__global__ __launch_bounds__(128) void k_post(const float* __restrict__ wp) {
    __shared__ float sA[32][68];
    __shared__ float sB[32][132];
    const int tid = threadIdx.x;
    const int tx = tid & 15;
    const int ty = tid >> 4;
    const int m0 = blockIdx.x * 64;
    const int kb0 = blockIdx.y * 96;

    float acc[8][8];
    #pragma unroll
    for (int i = 0; i < 8; ++i)
        #pragma unroll
        for (int j = 0; j < 8; ++j) acc[i][j] = 0.0f;

    for (int kc = 0; kc < 96; kc += 32) {
        const int kb = kb0 + kc;
        #pragma unroll
        for (int i = 0; i < 4; ++i) {               // A: 64m x 32k
            int f = tid + i*128;
            int mm = f >> 3, kq = (f & 7) << 2;
            float4 vv = *(const float4*)(g_x + (m0+mm)*GC + kb + kq);
            sA[kq+0][mm] = vv.x; sA[kq+1][mm] = vv.y;
            sA[kq+2][mm] = vv.z; sA[kq+3][mm] = vv.w;
        }
        #pragma unroll
        for (int i = 0; i < 8; ++i) {               // B: 128n x 32k
            int f = tid + i*128;
            int nr = f >> 3, kq = (f & 7) << 2;
            float4 vv = *(const float4*)(wp + nr*GC + kb + kq);
            sB[kq+0][nr] = vv.x; sB[kq+1][nr] = vv.y;
            sB[kq+2][nr] = vv.z; sB[kq+3][nr] = vv.w;
        }
        __syncthreads();
        #pragma unroll
        for (int k = 0; k < 32; ++k) {
            float av[8], bv[8];
            *(float4*)&av[0] = *(const float4*)&sA[k][ty*8];
            *(float4*)&av[4] = *(const float4*)&sA[k][ty*8 + 4];
            *(float4*)&bv[0] = *(const float4*)&sB[k][tx*4];
            *(float4*)&bv[4] = *(const float4*)&sB[k][64 + tx*4];
            #pragma unroll
            for (int i = 0; i < 8; ++i)
                #pragma unroll
                for (int j = 0; j < 8; ++j)
                    acc[i][j] = fmaf(av[i], bv[j], acc[i][j]);
        }
        __syncthreads();
    }

    float* dst = g_part[blockIdx.y];
    #pragma unroll
    for (int i = 0; i < 8; ++i) {
        int mrow = m0 + ty*8 + i;
        *(float4*)(dst + mrow*CPOST + tx*4)      = *(float4*)&acc[i][0];
        *(float4*)(dst + mrow*CPOST + 64 + tx*4) = *(float4*)&acc[i][4];
    }
}

// ---------------------------------------------------------------------------
// K_fin: sum split-K partials + BN2 + ReLU
// ---------------------------------------------------------------------------
__global__ void k_fin(const float* __restrict__ g2, const float* __restrict__ b2,
                      const float* __restrict__ mu2, const float* __restrict__ v2,
                      float* __restrict__ out) {
    int t = blockIdx.x * 256 + threadIdx.x;
    if (t >= BM*CPOST) return;
    int c = t & 127;
    float s = 0.0f;
    #pragma unroll
    for (int k = 0; k < KSPLIT; ++k) s += g_part[k][t];
    float scale = g2[c] * rsqrtf(v2[c] + 1e-5f);
    float shift = b2[c] - mu2[c]*scale;
    out[t] = fmaxf(fmaf(s, scale, shift), 0.0f);
}

// ---------------------------------------------------------------------------
extern "C" void kernel_launch(void* const* d_in, const int* in_sizes, int n_in,
                              void* d_out, int out_size) {
    const float* sxyz  = (const float*)d_in[0];
    const float* sfeat = (const float*)d_in[1];
    const float* nxyz  = (const float*)d_in[2];
    const float* wg    = (const float*)d_in[3];
    const float* g1    = (const float*)d_in[4];
    const float* b1    = (const float*)d_in[5];
    const float* m1    = (const float*)d_in[6];
    const float* v1    = (const float*)d_in[7];
    const float* wp    = (const float*)d_in[8];
    const float* g2    = (const float*)d_in[9];
    const float* b2    = (const float*)d_in[10];
    const float* m2    = (const float*)d_in[11];
    const float* v2    = (const float*)d_in[12];
    float* out = (float*)d_out;

    k_wt<<<(GG*41*CAGG + 255)/256, 256>>>(wg, g1, b1, m1, v1);
    k_bin<<<BB, 256>>>(sxyz);
    k_reduce<<<(BB*NN*32 + 255)/256, 256>>>(sfeat);
    k_nn<<<NCENT/16, 256>>>(nxyz);
    k_post<<<dim3(BM/64, KSPLIT), 128>>>(wp);
    k_fin<<<(BM*CPOST + 255)/256, 256>>>(g2, b2, m2, v2, out);
}

// round 13
// speedup vs baseline: 1.1642x; 1.0764x over previous
#include <cuda_runtime.h>
#include <math_constants.h>

#define BB 2
#define NN 2048
#define MM 512
#define GG 27
#define CAGG 32
#define CPOST 128
#define GC (GG*CAGG)      // 864
#define BM (BB*MM)        // 1024
#define NCENT (BM*GG)     // 27648
#define NCELL 512         // 8^3 grid
#define HCELL 1.25f
#define INVH 0.8f
#define KSPLIT 9

// Scratch (device globals; allocation is forbidden)
__device__ __align__(16) float4 g_pts4[BB][NN];          // binned points
__device__ int   g_cstart[BB][NCELL+1];
__device__ int   g_perm[BB][NN];
__device__ __align__(16) float g_feats[BB*NN*32];        // binned reduced feats
__device__ __align__(16) float g_wT[GG*41*CAGG];         // weights [g][i][o]
__device__ __align__(16) float g_sc1[GC], g_sh1[GC];     // folded BN1
__device__ __align__(16) float g_x[BM*GC];               // grouped-conv out
__device__ __align__(16) float g_part[KSPLIT][BM*CPOST]; // split-K partials

// ---------------------------------------------------------------------------
// K_pre: blocks 0..BB-1: per-batch counting sort (1024 threads).
//        blocks BB.. : weight transpose [g][i][o] + BN1 fold.
// ---------------------------------------------------------------------------
__global__ __launch_bounds__(1024) void k_pre(
        const float* __restrict__ sxyz, const float* __restrict__ wg,
        const float* __restrict__ g1, const float* __restrict__ b1,
        const float* __restrict__ mu1, const float* __restrict__ v1) {
    const int tid = threadIdx.x;
    if (blockIdx.x >= BB) {
        int t = (blockIdx.x - BB) * 1024 + tid;
        if (t < GG*41*CAGG) {
            int g = t / (41*CAGG);
            int rm = t - g*(41*CAGG);
            int i = rm >> 5, o = rm & 31;
            g_wT[t] = wg[g*(CAGG*41) + o*41 + i];
        }
        if (t < GC) {
            float sc = g1[t] * rsqrtf(v1[t] + 1e-5f);
            g_sc1[t] = sc;
            g_sh1[t] = b1[t] - mu1[t]*sc;
        }
        return;
    }
    __shared__ int cnt[NCELL];
    __shared__ int start[NCELL+1];
    const int b = blockIdx.x;
    for (int c = tid; c < NCELL; c += 1024) cnt[c] = 0;
    __syncthreads();
    for (int p = tid; p < NN; p += 1024) {
        const float* s = sxyz + (b*NN + p)*3;
        int cx = min(max((int)floorf(s[0]*INVH), 0), 7);
        int cy = min(max((int)floorf(s[1]*INVH), 0), 7);
        int cz = min(max((int)floorf(s[2]*INVH), 0), 7);
        atomicAdd(&cnt[(cx*8+cy)*8+cz], 1);
    }
    __syncthreads();
    if (tid < 32) {                      // warp-serial prefix over 512 cells
        int base = tid*16, s = 0;
        #pragma unroll
        for (int i = 0; i < 16; ++i) s += cnt[base+i];
        int inc = s;
        #pragma unroll
        for (int o = 1; o < 32; o <<= 1) {
            int v = __shfl_up_sync(0xffffffffu, inc, o);
            if (tid >= o) inc += v;
        }
        int run = inc - s;
        #pragma unroll
        for (int i = 0; i < 16; ++i) { start[base+i] = run; run += cnt[base+i]; }
        if (tid == 31) start[NCELL] = run;
    }
    __syncthreads();
    for (int c = tid; c < NCELL; c += 1024) cnt[c] = start[c];
    __syncthreads();
    for (int p = tid; p < NN; p += 1024) {
        const float* s = sxyz + (b*NN + p)*3;
        float x = s[0], y = s[1], z = s[2];
        int cx = min(max((int)floorf(x*INVH), 0), 7);
        int cy = min(max((int)floorf(y*INVH), 0), 7);
        int cz = min(max((int)floorf(z*INVH), 0), 7);
        int pos = atomicAdd(&cnt[(cx*8+cy)*8+cz], 1);
        g_pts4[b][pos] = make_float4(x, y, z, 0.0f);
        g_perm[b][pos] = p;
    }
    for (int c = tid; c <= NCELL; c += 1024) g_cstart[b][c] = start[c];
}

// ---------------------------------------------------------------------------
// K_reduce: channel reduction 128->32 gathered into binned order
// ---------------------------------------------------------------------------
__global__ void k_reduce(const float* __restrict__ sf) {
    int t = blockIdx.x * 256 + threadIdx.x;
    if (t >= BB*NN*32) return;
    int row = t >> 5, c = t & 31;
    int b = row / NN, p = row - b*NN;
    int orig = g_perm[b][p];
    const float* q = sf + (b*NN + orig)*128 + c;
    g_feats[t] = q[0] + q[32] + q[64] + q[96];
}

// Branchless insert of (d,i) into sorted triple d0<=d1<=d2
__device__ __forceinline__ void ins3(float d, int i,
        float& d0, int& i0, float& d1, int& i1, float& d2, int& i2) {
    bool c2 = d < d2, c1 = d < d1, c0 = d < d0;
    d2 = c1 ? d1 : (c2 ? d : d2);  i2 = c1 ? i1 : (c2 ? i : i2);
    d1 = c0 ? d0 : (c1 ? d : d1);  i1 = c0 ? i0 : (c1 ? i : i1);
    d0 = c0 ? d  : d0;             i0 = c0 ? i  : i0;
}

// ---------------------------------------------------------------------------
// K_nn: grid 3-NN per center (16-lane groups) + interp + FUSED grouped conv
// + BN1 + ReLU. Box-growing ring scan as contiguous z-runs; cheap count-based
// termination (redux), top-3 merge deferred to ONE pass. Writes g_x.
// (exact R10 configuration — measured 35.9us)
// ---------------------------------------------------------------------------
__global__ __launch_bounds__(256) void k_nn(const float* __restrict__ nxyz) {
    __shared__ __align__(16) float sv[16][48];   // staged vec[41] per group
    __shared__ int cst[NCELL+1];
    const int tid = threadIdx.x;
    const int grp = tid >> 4;
    const int l   = tid & 15;
    const unsigned gmask = 0xffffu << (tid & 16);   // group-local mask
    const int cid = blockIdx.x*16 + grp;
    const int b   = (blockIdx.x*16) / (MM*GG);   // never straddles batches

    for (int i = tid; i < NCELL+1; i += 256) cst[i] = g_cstart[b][i];
    __syncthreads();

    const int m = cid / GG, g = cid - m*GG;
    const int ixg = g / 9;
    const int iyg = (g - ixg*9) / 3;
    const int izg = g - ixg*9 - iyg*3;
    const float cx = nxyz[m*3+0] + __fadd_rn(__fmul_rn((float)ixg + 0.5f, 1.6f), -2.4f);
    const float cy = nxyz[m*3+1] + __fadd_rn(__fmul_rn((float)iyg + 0.5f, 1.6f), -2.4f);
    const float cz = nxyz[m*3+2] + __fadd_rn(__fmul_rn((float)izg + 0.5f, 1.6f), -2.4f);
    const int icx = (int)floorf(cx * INVH);
    const int icy = (int)floorf(cy * INVH);
    const int icz = (int)floorf(cz * INVH);

    const float INF = CUDART_INF_F;
    float d0 = INF, d1 = INF, d2v = INF;   // per-lane triple (disjoint sets)
    int   i0 = -1,  i1 = -1,  i2 = -1;

    const float4* __restrict__ pts = g_pts4[b];

    // box-growing scan; prev box tracked for ring = newbox \ prevbox
    int xlo = 1, xhi = 0, ylo = 1, yhi = 0, zlo = 1, zhi = 0;  // empty
    bool havePrev = false;

    for (int r = 1; r <= 10; ++r) {
        const int nxlo = max(icx-r, 0), nxhi = min(icx+r, 7);
        const int nylo = max(icy-r, 0), nyhi = min(icy+r, 7);
        const int nzlo = max(icz-r, 0), nzhi = min(icz+r, 7);
        const bool valid = (nxhi >= nxlo) && (nyhi >= nylo) && (nzhi >= nzlo);
        if (valid) {
            for (int x = nxlo; x <= nxhi; ++x)
            for (int y = nylo; y <= nyhi; ++y) {
                const int base = (x*8 + y)*8;
                const bool rowPrev = havePrev &&
                    x >= xlo && x <= xhi && y >= ylo && y <= yhi;
                int al, ah, bl, bh;
                if (rowPrev) { al = nzlo; ah = zlo-1; bl = zhi+1; bh = nzhi; }
                else         { al = nzlo; ah = nzhi;  bl = 1;     bh = 0;   }
                if (ah >= al) {
                    const int s = cst[base+al], e = cst[base+ah+1];
                    for (int j = s + l; j < e; j += 16) {
                        float4 p = __ldg(&pts[j]);
                        float dx = cx - p.x, dy = cy - p.y, dz = cz - p.z;
                        float dsq = fmaf(dx, dx, fmaf(dy, dy, dz*dz));
                        float ch  = fmaxf(fabsf(dx), fmaxf(fabsf(dy), fabsf(dz)));
                        float dd  = (ch <= 4.8f) ? dsq : INF;
                        ins3(dd, j, d0, i0, d1, i1, d2v, i2);
                    }
                }
                if (bh >= bl) {
                    const int s = cst[base+bl], e = cst[base+bh+1];
                    for (int j = s + l; j < e; j += 16) {
                        float4 p = __ldg(&pts[j]);
                        float dx = cx - p.x, dy = cy - p.y, dz = cz - p.z;
                        float dsq = fmaf(dx, dx, fmaf(dy, dy, dz*dz));
                        float ch  = fmaxf(fabsf(dx), fmaxf(fabsf(dy), fabsf(dz)));
                        float dd  = (ch <= 4.8f) ? dsq : INF;
                        ins3(dd, j, d0, i0, d1, i1, d2v, i2);
                    }
                }
            }
            xlo = nxlo; xhi = nxhi; ylo = nylo; yhi = nyhi; zlo = nzlo; zhi = nzhi;
            havePrev = true;

            // termination: distance from c to nearest UNSCANNED slab
            float bound = INF;
            if (xlo > 0) bound = fminf(bound, cx - (float)xlo*HCELL);
            if (xhi < 7) bound = fminf(bound, (float)(xhi+1)*HCELL - cx);
            if (ylo > 0) bound = fminf(bound, cy - (float)ylo*HCELL);
            if (yhi < 7) bound = fminf(bound, (float)(yhi+1)*HCELL - cy);
            if (zlo > 0) bound = fminf(bound, cz - (float)zlo*HCELL);
            if (zhi < 7) bound = fminf(bound, (float)(zhi+1)*HCELL - cz);
            if (bound == INF) break;          // whole grid scanned
            bound -= 1e-3f;                   // fp cell-assignment margin
            if (bound > 0.0f) {
                float b2 = bound * bound;
                unsigned cnt = (unsigned)(d0 < b2) + (unsigned)(d1 < b2)
                             + (unsigned)(d2v < b2);
                if (__reduce_add_sync(gmask, cnt) >= 3) break;
            }
        }
    }

    // ONE merge of per-lane triples -> global top-3 (group-local mask)
    float td0 = d0, td1 = d1, td2 = d2v;
    int   ti0 = i0, ti1 = i1, ti2 = i2;
    #pragma unroll
    for (int s = 1; s < 16; s <<= 1) {
        float e0 = __shfl_xor_sync(gmask, td0, s);
        int   j0 = __shfl_xor_sync(gmask, ti0, s);
        float e1 = __shfl_xor_sync(gmask, td1, s);
        int   j1 = __shfl_xor_sync(gmask, ti1, s);
        float e2 = __shfl_xor_sync(gmask, td2, s);
        int   j2 = __shfl_xor_sync(gmask, ti2, s);
        ins3(e0, j0, td0, ti0, td1, ti1, td2, ti2);
        ins3(e1, j1, td0, ti0, td1, ti1, td2, ti2);
        ins3(e2, j2, td0, ti0, td1, ti1, td2, ti2);
    }

    const bool empty = !(td0 < INF);
    float r0 = (td0 < INF) ? 1.0f/(td0 + 1e-8f) : 0.0f;
    float r1 = (td1 < INF) ? 1.0f/(td1 + 1e-8f) : 0.0f;
    float r2 = (td2 < INF) ? 1.0f/(td2 + 1e-8f) : 0.0f;
    float ssum = fmaxf(r0 + r1 + r2, 1e-8f);
    float w0 = r0/ssum, w1 = r1/ssum, w2 = r2/ssum;
    if (ti0 < 0) ti0 = 0;
    if (ti1 < 0) ti1 = ti0;
    if (ti2 < 0) ti2 = ti0;

    // interp: lane handles 2 feature channels (float2) -> stage to smem
    {
        const float2* F0 = (const float2*)(g_feats + (b*NN + ti0)*32);
        const float2* F1 = (const float2*)(g_feats + (b*NN + ti1)*32);
        const float2* F2 = (const float2*)(g_feats + (b*NN + ti2)*32);
        float2 a = __ldg(&F0[l]), u = __ldg(&F1[l]), v = __ldg(&F2[l]);
        float2 f;
        f.x = empty ? 0.0f : (w0*a.x + w1*u.x + w2*v.x);
        f.y = empty ? 0.0f : (w0*a.y + w1*u.y + w2*v.y);
        ((float2*)sv[grp])[l] = f;
        if (l < 3) {
            int isel = (l == 0) ? ti0 : ((l == 1) ? ti1 : ti2);
            float4 p = __ldg(&pts[isel]);
            sv[grp][32 + l*3 + 0] = empty ? 0.0f : (cx - p.x);
            sv[grp][32 + l*3 + 1] = empty ? 0.0f : (cy - p.y);
            sv[grp][32 + l*3 + 2] = empty ? 0.0f : (cz - p.z);
        }
    }
    __syncwarp();

    // fused grouped conv: lane computes output channels 2l, 2l+1
    const float* wrow = g_wT + g*(41*CAGG) + 2*l;
    float a0 = 0.0f, a1 = 0.0f;
    #pragma unroll
    for (int i = 0; i < 41; ++i) {
        float vi = sv[grp][i];
        float2 w = *(const float2*)(wrow + i*CAGG);
        a0 = fmaf(vi, w.x, a0);
        a1 = fmaf(vi, w.y, a1);
    }
    const int gc = g*CAGG + 2*l;
    float2 r;
    r.x = fmaxf(fmaf(a0, __ldg(&g_sc1[gc]),   __ldg(&g_sh1[gc])),   0.0f);
    r.y = fmaxf(fmaf(a1, __ldg(&g_sc1[gc+1]), __ldg(&g_sh1[gc+1])), 0.0f);
    *(float2*)(g_x + m*GC + gc) = r;
}

// ---------------------------------------------------------------------------
// K_post: split-K GEMM partials. CTA tile 64m x 128n, k=96 per split.
// ---------------------------------------------------------------------------
__global__ __launch_bounds__(128) void k_post(const float* __restrict__ wp) {
    __shared__ float sA[32][68];
    __shared__ float sB[32][132];
    const int tid = threadIdx.x;
    const int tx = tid & 15;
    const int ty = tid >> 4;
    const int m0 = blockIdx.x * 64;
    const int kb0 = blockIdx.y * 96;

    float acc[8][8];
    #pragma unroll
    for (int i = 0; i < 8; ++i)
        #pragma unroll
        for (int j = 0; j < 8; ++j) acc[i][j] = 0.0f;

    for (int kc = 0; kc < 96; kc += 32) {
        const int kb = kb0 + kc;
        #pragma unroll
        for (int i = 0; i < 4; ++i) {               // A: 64m x 32k
            int f = tid + i*128;
            int mm = f >> 3, kq = (f & 7) << 2;
            float4 vv = *(const float4*)(g_x + (m0+mm)*GC + kb + kq);
            sA[kq+0][mm] = vv.x; sA[kq+1][mm] = vv.y;
            sA[kq+2][mm] = vv.z; sA[kq+3][mm] = vv.w;
        }
        #pragma unroll
        for (int i = 0; i < 8; ++i) {               // B: 128n x 32k
            int f = tid + i*128;
            int nr = f >> 3, kq = (f & 7) << 2;
            float4 vv = *(const float4*)(wp + nr*GC + kb + kq);
            sB[kq+0][nr] = vv.x; sB[kq+1][nr] = vv.y;
            sB[kq+2][nr] = vv.z; sB[kq+3][nr] = vv.w;
        }
        __syncthreads();
        #pragma unroll
        for (int k = 0; k < 32; ++k) {
            float av[8], bv[8];
            *(float4*)&av[0] = *(const float4*)&sA[k][ty*8];
            *(float4*)&av[4] = *(const float4*)&sA[k][ty*8 + 4];
            *(float4*)&bv[0] = *(const float4*)&sB[k][tx*4];
            *(float4*)&bv[4] = *(const float4*)&sB[k][64 + tx*4];
            #pragma unroll
            for (int i = 0; i < 8; ++i)
                #pragma unroll
                for (int j = 0; j < 8; ++j)
                    acc[i][j] = fmaf(av[i], bv[j], acc[i][j]);
        }
        __syncthreads();
    }

    float* dst = g_part[blockIdx.y];
    #pragma unroll
    for (int i = 0; i < 8; ++i) {
        int mrow = m0 + ty*8 + i;
        *(float4*)(dst + mrow*CPOST + tx*4)      = *(float4*)&acc[i][0];
        *(float4*)(dst + mrow*CPOST + 64 + tx*4) = *(float4*)&acc[i][4];
    }
}

// ---------------------------------------------------------------------------
// K_fin: sum split-K partials + BN2 + ReLU
// ---------------------------------------------------------------------------
__global__ void k_fin(const float* __restrict__ g2, const float* __restrict__ b2,
                      const float* __restrict__ mu2, const float* __restrict__ v2,
                      float* __restrict__ out) {
    int t = blockIdx.x * 256 + threadIdx.x;
    if (t >= BM*CPOST) return;
    int c = t & 127;
    float s = 0.0f;
    #pragma unroll
    for (int k = 0; k < KSPLIT; ++k) s += g_part[k][t];
    float scale = g2[c] * rsqrtf(v2[c] + 1e-5f);
    float shift = b2[c] - mu2[c]*scale;
    out[t] = fmaxf(fmaf(s, scale, shift), 0.0f);
}

// ---------------------------------------------------------------------------
extern "C" void kernel_launch(void* const* d_in, const int* in_sizes, int n_in,
                              void* d_out, int out_size) {
    const float* sxyz  = (const float*)d_in[0];
    const float* sfeat = (const float*)d_in[1];
    const float* nxyz  = (const float*)d_in[2];
    const float* wg    = (const float*)d_in[3];
    const float* g1    = (const float*)d_in[4];
    const float* b1    = (const float*)d_in[5];
    const float* m1    = (const float*)d_in[6];
    const float* v1    = (const float*)d_in[7];
    const float* wp    = (const float*)d_in[8];
    const float* g2    = (const float*)d_in[9];
    const float* b2    = (const float*)d_in[10];
    const float* m2    = (const float*)d_in[11];
    const float* v2    = (const float*)d_in[12];
    float* out = (float*)d_out;

    const int wtBlocks = (GG*41*CAGG + 1023) / 1024;      // 35
    k_pre<<<BB + wtBlocks, 1024>>>(sxyz, wg, g1, b1, m1, v1);
    k_reduce<<<(BB*NN*32 + 255)/256, 256>>>(sfeat);
    k_nn<<<NCENT/16, 256>>>(nxyz);
    k_post<<<dim3(BM/64, KSPLIT), 128>>>(wp);
    k_fin<<<(BM*CPOST + 255)/256, 256>>>(g2, b2, m2, v2, out);
}

// round 14
// speedup vs baseline: 1.2064x; 1.0363x over previous
#include <cuda_runtime.h>
#include <math_constants.h>

#define BB 2
#define NN 2048
#define MM 512
#define GG 27
#define CAGG 32
#define CPOST 128
#define GC (GG*CAGG)      // 864
#define BM (BB*MM)        // 1024
#define NCENT (BM*GG)     // 27648
#define NCELL 512         // 8^3 grid
#define HCELL 1.25f
#define INVH 0.8f
#define KSPLIT 27

// Scratch (device globals; allocation is forbidden)
__device__ __align__(16) float4 g_pts4[BB][NN];          // binned points
__device__ int   g_cstart[BB][NCELL+1];
__device__ int   g_perm[BB][NN];
__device__ __align__(16) float g_feats[BB*NN*32];        // binned reduced feats
__device__ __align__(16) float g_wT[GG*41*CAGG];         // weights [g][i][o]
__device__ __align__(16) float g_sc1[GC], g_sh1[GC];     // folded BN1
__device__ __align__(16) float g_x[BM*GC];               // grouped-conv out
__device__ __align__(16) float g_part[KSPLIT][BM*CPOST]; // split-K partials

// ---------------------------------------------------------------------------
// K_pre: blocks 0..BB-1: per-batch counting sort (1024 threads).
//        blocks BB.. : weight transpose [g][i][o] + BN1 fold.
// ---------------------------------------------------------------------------
__global__ __launch_bounds__(1024) void k_pre(
        const float* __restrict__ sxyz, const float* __restrict__ wg,
        const float* __restrict__ g1, const float* __restrict__ b1,
        const float* __restrict__ mu1, const float* __restrict__ v1) {
    const int tid = threadIdx.x;
    if (blockIdx.x >= BB) {
        int t = (blockIdx.x - BB) * 1024 + tid;
        if (t < GG*41*CAGG) {
            int g = t / (41*CAGG);
            int rm = t - g*(41*CAGG);
            int i = rm >> 5, o = rm & 31;
            g_wT[t] = wg[g*(CAGG*41) + o*41 + i];
        }
        if (t < GC) {
            float sc = g1[t] * rsqrtf(v1[t] + 1e-5f);
            g_sc1[t] = sc;
            g_sh1[t] = b1[t] - mu1[t]*sc;
        }
        return;
    }
    __shared__ int cnt[NCELL];
    __shared__ int start[NCELL+1];
    const int b = blockIdx.x;
    for (int c = tid; c < NCELL; c += 1024) cnt[c] = 0;
    __syncthreads();
    for (int p = tid; p < NN; p += 1024) {
        const float* s = sxyz + (b*NN + p)*3;
        int cx = min(max((int)floorf(s[0]*INVH), 0), 7);
        int cy = min(max((int)floorf(s[1]*INVH), 0), 7);
        int cz = min(max((int)floorf(s[2]*INVH), 0), 7);
        atomicAdd(&cnt[(cx*8+cy)*8+cz], 1);
    }
    __syncthreads();
    if (tid < 32) {                      // warp-serial prefix over 512 cells
        int base = tid*16, s = 0;
        #pragma unroll
        for (int i = 0; i < 16; ++i) s += cnt[base+i];
        int inc = s;
        #pragma unroll
        for (int o = 1; o < 32; o <<= 1) {
            int v = __shfl_up_sync(0xffffffffu, inc, o);
            if (tid >= o) inc += v;
        }
        int run = inc - s;
        #pragma unroll
        for (int i = 0; i < 16; ++i) { start[base+i] = run; run += cnt[base+i]; }
        if (tid == 31) start[NCELL] = run;
    }
    __syncthreads();
    for (int c = tid; c < NCELL; c += 1024) cnt[c] = start[c];
    __syncthreads();
    for (int p = tid; p < NN; p += 1024) {
        const float* s = sxyz + (b*NN + p)*3;
        float x = s[0], y = s[1], z = s[2];
        int cx = min(max((int)floorf(x*INVH), 0), 7);
        int cy = min(max((int)floorf(y*INVH), 0), 7);
        int cz = min(max((int)floorf(z*INVH), 0), 7);
        int pos = atomicAdd(&cnt[(cx*8+cy)*8+cz], 1);
        g_pts4[b][pos] = make_float4(x, y, z, 0.0f);
        g_perm[b][pos] = p;
    }
    for (int c = tid; c <= NCELL; c += 1024) g_cstart[b][c] = start[c];
}

// ---------------------------------------------------------------------------
// K_reduce: channel reduction 128->32 gathered into binned order
// ---------------------------------------------------------------------------
__global__ void k_reduce(const float* __restrict__ sf) {
    int t = blockIdx.x * 256 + threadIdx.x;
    if (t >= BB*NN*32) return;
    int row = t >> 5, c = t & 31;
    int b = row / NN, p = row - b*NN;
    int orig = g_perm[b][p];
    const float* q = sf + (b*NN + orig)*128 + c;
    g_feats[t] = q[0] + q[32] + q[64] + q[96];
}

// Branchless insert of (d,i) into sorted triple d0<=d1<=d2
__device__ __forceinline__ void ins3(float d, int i,
        float& d0, int& i0, float& d1, int& i1, float& d2, int& i2) {
    bool c2 = d < d2, c1 = d < d1, c0 = d < d0;
    d2 = c1 ? d1 : (c2 ? d : d2);  i2 = c1 ? i1 : (c2 ? i : i2);
    d1 = c0 ? d0 : (c1 ? d : d1);  i1 = c0 ? i0 : (c1 ? i : i1);
    d0 = c0 ? d  : d0;             i0 = c0 ? i  : i0;
}

// ---------------------------------------------------------------------------
// K_nn: grid 3-NN per center (16-lane groups) + interp + FUSED grouped conv
// + BN1 + ReLU. (exact R10 configuration — measured 35.9us)
// ---------------------------------------------------------------------------
__global__ __launch_bounds__(256) void k_nn(const float* __restrict__ nxyz) {
    __shared__ __align__(16) float sv[16][48];   // staged vec[41] per group
    __shared__ int cst[NCELL+1];
    const int tid = threadIdx.x;
    const int grp = tid >> 4;
    const int l   = tid & 15;
    const unsigned gmask = 0xffffu << (tid & 16);   // group-local mask
    const int cid = blockIdx.x*16 + grp;
    const int b   = (blockIdx.x*16) / (MM*GG);   // never straddles batches

    for (int i = tid; i < NCELL+1; i += 256) cst[i] = g_cstart[b][i];
    __syncthreads();

    const int m = cid / GG, g = cid - m*GG;
    const int ixg = g / 9;
    const int iyg = (g - ixg*9) / 3;
    const int izg = g - ixg*9 - iyg*3;
    const float cx = nxyz[m*3+0] + __fadd_rn(__fmul_rn((float)ixg + 0.5f, 1.6f), -2.4f);
    const float cy = nxyz[m*3+1] + __fadd_rn(__fmul_rn((float)iyg + 0.5f, 1.6f), -2.4f);
    const float cz = nxyz[m*3+2] + __fadd_rn(__fmul_rn((float)izg + 0.5f, 1.6f), -2.4f);
    const int icx = (int)floorf(cx * INVH);
    const int icy = (int)floorf(cy * INVH);
    const int icz = (int)floorf(cz * INVH);

    const float INF = CUDART_INF_F;
    float d0 = INF, d1 = INF, d2v = INF;   // per-lane triple (disjoint sets)
    int   i0 = -1,  i1 = -1,  i2 = -1;

    const float4* __restrict__ pts = g_pts4[b];

    // box-growing scan; prev box tracked for ring = newbox \ prevbox
    int xlo = 1, xhi = 0, ylo = 1, yhi = 0, zlo = 1, zhi = 0;  // empty
    bool havePrev = false;

    for (int r = 1; r <= 10; ++r) {
        const int nxlo = max(icx-r, 0), nxhi = min(icx+r, 7);
        const int nylo = max(icy-r, 0), nyhi = min(icy+r, 7);
        const int nzlo = max(icz-r, 0), nzhi = min(icz+r, 7);
        const bool valid = (nxhi >= nxlo) && (nyhi >= nylo) && (nzhi >= nzlo);
        if (valid) {
            for (int x = nxlo; x <= nxhi; ++x)
            for (int y = nylo; y <= nyhi; ++y) {
                const int base = (x*8 + y)*8;
                const bool rowPrev = havePrev &&
                    x >= xlo && x <= xhi && y >= ylo && y <= yhi;
                int al, ah, bl, bh;
                if (rowPrev) { al = nzlo; ah = zlo-1; bl = zhi+1; bh = nzhi; }
                else         { al = nzlo; ah = nzhi;  bl = 1;     bh = 0;   }
                if (ah >= al) {
                    const int s = cst[base+al], e = cst[base+ah+1];
                    for (int j = s + l; j < e; j += 16) {
                        float4 p = __ldg(&pts[j]);
                        float dx = cx - p.x, dy = cy - p.y, dz = cz - p.z;
                        float dsq = fmaf(dx, dx, fmaf(dy, dy, dz*dz));
                        float ch  = fmaxf(fabsf(dx), fmaxf(fabsf(dy), fabsf(dz)));
                        float dd  = (ch <= 4.8f) ? dsq : INF;
                        ins3(dd, j, d0, i0, d1, i1, d2v, i2);
                    }
                }
                if (bh >= bl) {
                    const int s = cst[base+bl], e = cst[base+bh+1];
                    for (int j = s + l; j < e; j += 16) {
                        float4 p = __ldg(&pts[j]);
                        float dx = cx - p.x, dy = cy - p.y, dz = cz - p.z;
                        float dsq = fmaf(dx, dx, fmaf(dy, dy, dz*dz));
                        float ch  = fmaxf(fabsf(dx), fmaxf(fabsf(dy), fabsf(dz)));
                        float dd  = (ch <= 4.8f) ? dsq : INF;
                        ins3(dd, j, d0, i0, d1, i1, d2v, i2);
                    }
                }
            }
            xlo = nxlo; xhi = nxhi; ylo = nylo; yhi = nyhi; zlo = nzlo; zhi = nzhi;
            havePrev = true;

            // termination: distance from c to nearest UNSCANNED slab
            float bound = INF;
            if (xlo > 0) bound = fminf(bound, cx - (float)xlo*HCELL);
            if (xhi < 7) bound = fminf(bound, (float)(xhi+1)*HCELL - cx);
            if (ylo > 0) bound = fminf(bound, cy - (float)ylo*HCELL);
            if (yhi < 7) bound = fminf(bound, (float)(yhi+1)*HCELL - cy);
            if (zlo > 0) bound = fminf(bound, cz - (float)zlo*HCELL);
            if (zhi < 7) bound = fminf(bound, (float)(zhi+1)*HCELL - cz);
            if (bound == INF) break;          // whole grid scanned
            bound -= 1e-3f;                   // fp cell-assignment margin
            if (bound > 0.0f) {
                float b2 = bound * bound;
                unsigned cnt = (unsigned)(d0 < b2) + (unsigned)(d1 < b2)
                             + (unsigned)(d2v < b2);
                if (__reduce_add_sync(gmask, cnt) >= 3) break;
            }
        }
    }

    // ONE merge of per-lane triples -> global top-3 (group-local mask)
    float td0 = d0, td1 = d1, td2 = d2v;
    int   ti0 = i0, ti1 = i1, ti2 = i2;
    #pragma unroll
    for (int s = 1; s < 16; s <<= 1) {
        float e0 = __shfl_xor_sync(gmask, td0, s);
        int   j0 = __shfl_xor_sync(gmask, ti0, s);
        float e1 = __shfl_xor_sync(gmask, td1, s);
        int   j1 = __shfl_xor_sync(gmask, ti1, s);
        float e2 = __shfl_xor_sync(gmask, td2, s);
        int   j2 = __shfl_xor_sync(gmask, ti2, s);
        ins3(e0, j0, td0, ti0, td1, ti1, td2, ti2);
        ins3(e1, j1, td0, ti0, td1, ti1, td2, ti2);
        ins3(e2, j2, td0, ti0, td1, ti1, td2, ti2);
    }

    const bool empty = !(td0 < INF);
    float r0 = (td0 < INF) ? 1.0f/(td0 + 1e-8f) : 0.0f;
    float r1 = (td1 < INF) ? 1.0f/(td1 + 1e-8f) : 0.0f;
    float r2 = (td2 < INF) ? 1.0f/(td2 + 1e-8f) : 0.0f;
    float ssum = fmaxf(r0 + r1 + r2, 1e-8f);
    float w0 = r0/ssum, w1 = r1/ssum, w2 = r2/ssum;
    if (ti0 < 0) ti0 = 0;
    if (ti1 < 0) ti1 = ti0;
    if (ti2 < 0) ti2 = ti0;

    // interp: lane handles 2 feature channels (float2) -> stage to smem
    {
        const float2* F0 = (const float2*)(g_feats + (b*NN + ti0)*32);
        const float2* F1 = (const float2*)(g_feats + (b*NN + ti1)*32);
        const float2* F2 = (const float2*)(g_feats + (b*NN + ti2)*32);
        float2 a = __ldg(&F0[l]), u = __ldg(&F1[l]), v = __ldg(&F2[l]);
        float2 f;
        f.x = empty ? 0.0f : (w0*a.x + w1*u.x + w2*v.x);
        f.y = empty ? 0.0f : (w0*a.y + w1*u.y + w2*v.y);
        ((float2*)sv[grp])[l] = f;
        if (l < 3) {
            int isel = (l == 0) ? ti0 : ((l == 1) ? ti1 : ti2);
            float4 p = __ldg(&pts[isel]);
            sv[grp][32 + l*3 + 0] = empty ? 0.0f : (cx - p.x);
            sv[grp][32 + l*3 + 1] = empty ? 0.0f : (cy - p.y);
            sv[grp][32 + l*3 + 2] = empty ? 0.0f : (cz - p.z);
        }
    }
    __syncwarp();

    // fused grouped conv: lane computes output channels 2l, 2l+1
    const float* wrow = g_wT + g*(41*CAGG) + 2*l;
    float a0 = 0.0f, a1 = 0.0f;
    #pragma unroll
    for (int i = 0; i < 41; ++i) {
        float vi = sv[grp][i];
        float2 w = *(const float2*)(wrow + i*CAGG);
        a0 = fmaf(vi, w.x, a0);
        a1 = fmaf(vi, w.y, a1);
    }
    const int gc = g*CAGG + 2*l;
    float2 r;
    r.x = fmaxf(fmaf(a0, __ldg(&g_sc1[gc]),   __ldg(&g_sh1[gc])),   0.0f);
    r.y = fmaxf(fmaf(a1, __ldg(&g_sc1[gc+1]), __ldg(&g_sh1[gc+1])), 0.0f);
    *(float2*)(g_x + m*GC + gc) = r;
}

// ---------------------------------------------------------------------------
// K_post: split-K GEMM partials. CTA tile 64m x 128n, ONE k-chunk of 32.
// block 256: mq = tid>>5 (8 groups x 8m), nq = tid&31 (32 x 4n). 8x4 regs.
// grid (16, 27). A-frag loads are warp-uniform broadcasts.
// ---------------------------------------------------------------------------
__global__ __launch_bounds__(256) void k_post(const float* __restrict__ wp) {
    __shared__ float sA[32][68];    // [k][m] pitch 68 (16B-aligned rows)
    __shared__ float sB[32][132];   // [k][n] pitch 132
    const int tid = threadIdx.x;
    const int nq = tid & 31;
    const int mq = tid >> 5;
    const int m0 = blockIdx.x * 64;
    const int kb = blockIdx.y * 32;

    // A: 64m x 32k = 512 float4; 256 threads x 2
    #pragma unroll
    for (int i = 0; i < 2; ++i) {
        int f = tid + i*256;
        int mm = f >> 3, kq = (f & 7) << 2;
        float4 vv = *(const float4*)(g_x + (m0+mm)*GC + kb + kq);
        sA[kq+0][mm] = vv.x; sA[kq+1][mm] = vv.y;
        sA[kq+2][mm] = vv.z; sA[kq+3][mm] = vv.w;
    }
    // B: 128n x 32k = 1024 float4; 256 threads x 4
    #pragma unroll
    for (int i = 0; i < 4; ++i) {
        int f = tid + i*256;
        int nr = f >> 3, kq = (f & 7) << 2;
        float4 vv = *(const float4*)(wp + nr*GC + kb + kq);
        sB[kq+0][nr] = vv.x; sB[kq+1][nr] = vv.y;
        sB[kq+2][nr] = vv.z; sB[kq+3][nr] = vv.w;
    }
    __syncthreads();

    float acc[8][4];
    #pragma unroll
    for (int i = 0; i < 8; ++i)
        #pragma unroll
        for (int j = 0; j < 4; ++j) acc[i][j] = 0.0f;

    #pragma unroll
    for (int k = 0; k < 32; ++k) {
        float av[8], bv[4];
        *(float4*)&av[0] = *(const float4*)&sA[k][mq*8];
        *(float4*)&av[4] = *(const float4*)&sA[k][mq*8 + 4];
        *(float4*)&bv[0] = *(const float4*)&sB[k][nq*4];
        #pragma unroll
        for (int i = 0; i < 8; ++i)
            #pragma unroll
            for (int j = 0; j < 4; ++j)
                acc[i][j] = fmaf(av[i], bv[j], acc[i][j]);
    }

    float* dst = g_part[blockIdx.y];
    #pragma unroll
    for (int i = 0; i < 8; ++i) {
        int mrow = m0 + mq*8 + i;
        *(float4*)(dst + mrow*CPOST + nq*4) = *(float4*)&acc[i][0];
    }
}

// ---------------------------------------------------------------------------
// K_fin: sum split-K partials + BN2 + ReLU
// ---------------------------------------------------------------------------
__global__ void k_fin(const float* __restrict__ g2, const float* __restrict__ b2,
                      const float* __restrict__ mu2, const float* __restrict__ v2,
                      float* __restrict__ out) {
    int t = blockIdx.x * 256 + threadIdx.x;
    if (t >= BM*CPOST) return;
    int c = t & 127;
    float s = 0.0f;
    #pragma unroll
    for (int k = 0; k < KSPLIT; ++k) s += g_part[k][t];
    float scale = g2[c] * rsqrtf(v2[c] + 1e-5f);
    float shift = b2[c] - mu2[c]*scale;
    out[t] = fmaxf(fmaf(s, scale, shift), 0.0f);
}

// ---------------------------------------------------------------------------
extern "C" void kernel_launch(void* const* d_in, const int* in_sizes, int n_in,
                              void* d_out, int out_size) {
    const float* sxyz  = (const float*)d_in[0];
    const float* sfeat = (const float*)d_in[1];
    const float* nxyz  = (const float*)d_in[2];
    const float* wg    = (const float*)d_in[3];
    const float* g1    = (const float*)d_in[4];
    const float* b1    = (const float*)d_in[5];
    const float* m1    = (const float*)d_in[6];
    const float* v1    = (const float*)d_in[7];
    const float* wp    = (const float*)d_in[8];
    const float* g2    = (const float*)d_in[9];
    const float* b2    = (const float*)d_in[10];
    const float* m2    = (const float*)d_in[11];
    const float* v2    = (const float*)d_in[12];
    float* out = (float*)d_out;

    const int wtBlocks = (GG*41*CAGG + 1023) / 1024;      // 35
    k_pre<<<BB + wtBlocks, 1024>>>(sxyz, wg, g1, b1, m1, v1);
    k_reduce<<<(BB*NN*32 + 255)/256, 256>>>(sfeat);
    k_nn<<<NCENT/16, 256>>>(nxyz);
    k_post<<<dim3(BM/64, KSPLIT), 256>>>(wp);
    k_fin<<<(BM*CPOST + 255)/256, 256>>>(g2, b2, m2, v2, out);
}

// round 15
// speedup vs baseline: 1.2649x; 1.0485x over previous
#include <cuda_runtime.h>
#include <math_constants.h>

#define BB 2
#define NN 2048
#define MM 512
#define GG 27
#define CAGG 32
#define CPOST 128
#define GC (GG*CAGG)      // 864
#define BM (BB*MM)        // 1024
#define NCENT (BM*GG)     // 27648
#define NCELL 512         // 8^3 grid
#define HCELL 1.25f
#define INVH 0.8f
#define KSPLIT 27

// Scratch (device globals; allocation is forbidden)
__device__ __align__(16) float4 g_pts4[BB][NN];          // binned points
__device__ int   g_cstart[BB][NCELL+1];
__device__ int   g_perm[BB][NN];
__device__ __align__(16) float g_feats[BB*NN*32];        // binned reduced feats
__device__ __align__(16) float g_wT[GG*41*CAGG];         // weights [g][i][o]
__device__ __align__(16) float g_sc1[GC], g_sh1[GC];     // folded BN1
__device__ __align__(16) float g_x[BM*GC];               // grouped-conv out
__device__ __align__(16) float g_part[KSPLIT][BM*CPOST]; // split-K partials

// ---------------------------------------------------------------------------
// K_pre: blocks 0..BB-1: per-batch counting sort (1024 threads).
//        blocks BB.. : weight transpose [g][i][o] + BN1 fold.
// ---------------------------------------------------------------------------
__global__ __launch_bounds__(1024) void k_pre(
        const float* __restrict__ sxyz, const float* __restrict__ wg,
        const float* __restrict__ g1, const float* __restrict__ b1,
        const float* __restrict__ mu1, const float* __restrict__ v1) {
    const int tid = threadIdx.x;
    if (blockIdx.x >= BB) {
        int t = (blockIdx.x - BB) * 1024 + tid;
        if (t < GG*41*CAGG) {
            int g = t / (41*CAGG);
            int rm = t - g*(41*CAGG);
            int i = rm >> 5, o = rm & 31;
            g_wT[t] = wg[g*(CAGG*41) + o*41 + i];
        }
        if (t < GC) {
            float sc = g1[t] * rsqrtf(v1[t] + 1e-5f);
            g_sc1[t] = sc;
            g_sh1[t] = b1[t] - mu1[t]*sc;
        }
        return;
    }
    __shared__ int cnt[NCELL];
    __shared__ int start[NCELL+1];
    const int b = blockIdx.x;
    for (int c = tid; c < NCELL; c += 1024) cnt[c] = 0;
    __syncthreads();
    for (int p = tid; p < NN; p += 1024) {
        const float* s = sxyz + (b*NN + p)*3;
        int cx = min(max((int)floorf(s[0]*INVH), 0), 7);
        int cy = min(max((int)floorf(s[1]*INVH), 0), 7);
        int cz = min(max((int)floorf(s[2]*INVH), 0), 7);
        atomicAdd(&cnt[(cx*8+cy)*8+cz], 1);
    }
    __syncthreads();
    if (tid < 32) {                      // warp-serial prefix over 512 cells
        int base = tid*16, s = 0;
        #pragma unroll
        for (int i = 0; i < 16; ++i) s += cnt[base+i];
        int inc = s;
        #pragma unroll
        for (int o = 1; o < 32; o <<= 1) {
            int v = __shfl_up_sync(0xffffffffu, inc, o);
            if (tid >= o) inc += v;
        }
        int run = inc - s;
        #pragma unroll
        for (int i = 0; i < 16; ++i) { start[base+i] = run; run += cnt[base+i]; }
        if (tid == 31) start[NCELL] = run;
    }
    __syncthreads();
    for (int c = tid; c < NCELL; c += 1024) cnt[c] = start[c];
    __syncthreads();
    for (int p = tid; p < NN; p += 1024) {
        const float* s = sxyz + (b*NN + p)*3;
        float x = s[0], y = s[1], z = s[2];
        int cx = min(max((int)floorf(x*INVH), 0), 7);
        int cy = min(max((int)floorf(y*INVH), 0), 7);
        int cz = min(max((int)floorf(z*INVH), 0), 7);
        int pos = atomicAdd(&cnt[(cx*8+cy)*8+cz], 1);
        g_pts4[b][pos] = make_float4(x, y, z, 0.0f);
        g_perm[b][pos] = p;
    }
    for (int c = tid; c <= NCELL; c += 1024) g_cstart[b][c] = start[c];
}

// ---------------------------------------------------------------------------
// K_reduce: channel reduction 128->32 gathered into binned order (float4)
// thread t -> (row = t>>3, c4 = t&7): 4 LDG.128 + 12 add + 1 STG.128
// ---------------------------------------------------------------------------
__global__ void k_reduce(const float* __restrict__ sf) {
    int t = blockIdx.x * 256 + threadIdx.x;
    if (t >= BB*NN*8) return;
    int row = t >> 3, c4 = t & 7;
    int b = row / NN, p = row - b*NN;
    int orig = g_perm[b][p];
    const float4* q = (const float4*)(sf + (b*NN + orig)*128) + c4;
    float4 v0 = __ldg(q);
    float4 v1 = __ldg(q + 8);
    float4 v2 = __ldg(q + 16);
    float4 v3 = __ldg(q + 24);
    float4 s;
    s.x = (v0.x + v1.x) + (v2.x + v3.x);
    s.y = (v0.y + v1.y) + (v2.y + v3.y);
    s.z = (v0.z + v1.z) + (v2.z + v3.z);
    s.w = (v0.w + v1.w) + (v2.w + v3.w);
    ((float4*)g_feats)[row*8 + c4] = s;
}

// Branchless insert of (d,i) into sorted triple d0<=d1<=d2
__device__ __forceinline__ void ins3(float d, int i,
        float& d0, int& i0, float& d1, int& i1, float& d2, int& i2) {
    bool c2 = d < d2, c1 = d < d1, c0 = d < d0;
    d2 = c1 ? d1 : (c2 ? d : d2);  i2 = c1 ? i1 : (c2 ? i : i2);
    d1 = c0 ? d0 : (c1 ? d : d1);  i1 = c0 ? i0 : (c1 ? i : i1);
    d0 = c0 ? d  : d0;             i0 = c0 ? i  : i0;
}

// ---------------------------------------------------------------------------
// K_nn: grid 3-NN per center (16-lane groups) + interp + FUSED grouped conv
// + BN1 + ReLU. (exact R10 configuration — measured 35.9us)
// ---------------------------------------------------------------------------
__global__ __launch_bounds__(256) void k_nn(const float* __restrict__ nxyz) {
    __shared__ __align__(16) float sv[16][48];   // staged vec[41] per group
    __shared__ int cst[NCELL+1];
    const int tid = threadIdx.x;
    const int grp = tid >> 4;
    const int l   = tid & 15;
    const unsigned gmask = 0xffffu << (tid & 16);   // group-local mask
    const int cid = blockIdx.x*16 + grp;
    const int b   = (blockIdx.x*16) / (MM*GG);   // never straddles batches

    for (int i = tid; i < NCELL+1; i += 256) cst[i] = g_cstart[b][i];
    __syncthreads();

    const int m = cid / GG, g = cid - m*GG;
    const int ixg = g / 9;
    const int iyg = (g - ixg*9) / 3;
    const int izg = g - ixg*9 - iyg*3;
    const float cx = nxyz[m*3+0] + __fadd_rn(__fmul_rn((float)ixg + 0.5f, 1.6f), -2.4f);
    const float cy = nxyz[m*3+1] + __fadd_rn(__fmul_rn((float)iyg + 0.5f, 1.6f), -2.4f);
    const float cz = nxyz[m*3+2] + __fadd_rn(__fmul_rn((float)izg + 0.5f, 1.6f), -2.4f);
    const int icx = (int)floorf(cx * INVH);
    const int icy = (int)floorf(cy * INVH);
    const int icz = (int)floorf(cz * INVH);

    const float INF = CUDART_INF_F;
    float d0 = INF, d1 = INF, d2v = INF;   // per-lane triple (disjoint sets)
    int   i0 = -1,  i1 = -1,  i2 = -1;

    const float4* __restrict__ pts = g_pts4[b];

    // box-growing scan; prev box tracked for ring = newbox \ prevbox
    int xlo = 1, xhi = 0, ylo = 1, yhi = 0, zlo = 1, zhi = 0;  // empty
    bool havePrev = false;

    for (int r = 1; r <= 10; ++r) {
        const int nxlo = max(icx-r, 0), nxhi = min(icx+r, 7);
        const int nylo = max(icy-r, 0), nyhi = min(icy+r, 7);
        const int nzlo = max(icz-r, 0), nzhi = min(icz+r, 7);
        const bool valid = (nxhi >= nxlo) && (nyhi >= nylo) && (nzhi >= nzlo);
        if (valid) {
            for (int x = nxlo; x <= nxhi; ++x)
            for (int y = nylo; y <= nyhi; ++y) {
                const int base = (x*8 + y)*8;
                const bool rowPrev = havePrev &&
                    x >= xlo && x <= xhi && y >= ylo && y <= yhi;
                int al, ah, bl, bh;
                if (rowPrev) { al = nzlo; ah = zlo-1; bl = zhi+1; bh = nzhi; }
                else         { al = nzlo; ah = nzhi;  bl = 1;     bh = 0;   }
                if (ah >= al) {
                    const int s = cst[base+al], e = cst[base+ah+1];
                    for (int j = s + l; j < e; j += 16) {
                        float4 p = __ldg(&pts[j]);
                        float dx = cx - p.x, dy = cy - p.y, dz = cz - p.z;
                        float dsq = fmaf(dx, dx, fmaf(dy, dy, dz*dz));
                        float ch  = fmaxf(fabsf(dx), fmaxf(fabsf(dy), fabsf(dz)));
                        float dd  = (ch <= 4.8f) ? dsq : INF;
                        ins3(dd, j, d0, i0, d1, i1, d2v, i2);
                    }
                }
                if (bh >= bl) {
                    const int s = cst[base+bl], e = cst[base+bh+1];
                    for (int j = s + l; j < e; j += 16) {
                        float4 p = __ldg(&pts[j]);
                        float dx = cx - p.x, dy = cy - p.y, dz = cz - p.z;
                        float dsq = fmaf(dx, dx, fmaf(dy, dy, dz*dz));
                        float ch  = fmaxf(fabsf(dx), fmaxf(fabsf(dy), fabsf(dz)));
                        float dd  = (ch <= 4.8f) ? dsq : INF;
                        ins3(dd, j, d0, i0, d1, i1, d2v, i2);
                    }
                }
            }
            xlo = nxlo; xhi = nxhi; ylo = nylo; yhi = nyhi; zlo = nzlo; zhi = nzhi;
            havePrev = true;

            // termination: distance from c to nearest UNSCANNED slab
            float bound = INF;
            if (xlo > 0) bound = fminf(bound, cx - (float)xlo*HCELL);
            if (xhi < 7) bound = fminf(bound, (float)(xhi+1)*HCELL - cx);
            if (ylo > 0) bound = fminf(bound, cy - (float)ylo*HCELL);
            if (yhi < 7) bound = fminf(bound, (float)(yhi+1)*HCELL - cy);
            if (zlo > 0) bound = fminf(bound, cz - (float)zlo*HCELL);
            if (zhi < 7) bound = fminf(bound, (float)(zhi+1)*HCELL - cz);
            if (bound == INF) break;          // whole grid scanned
            bound -= 1e-3f;                   // fp cell-assignment margin
            if (bound > 0.0f) {
                float b2 = bound * bound;
                unsigned cnt = (unsigned)(d0 < b2) + (unsigned)(d1 < b2)
                             + (unsigned)(d2v < b2);
                if (__reduce_add_sync(gmask, cnt) >= 3) break;
            }
        }
    }

    // ONE merge of per-lane triples -> global top-3 (group-local mask)
    float td0 = d0, td1 = d1, td2 = d2v;
    int   ti0 = i0, ti1 = i1, ti2 = i2;
    #pragma unroll
    for (int s = 1; s < 16; s <<= 1) {
        float e0 = __shfl_xor_sync(gmask, td0, s);
        int   j0 = __shfl_xor_sync(gmask, ti0, s);
        float e1 = __shfl_xor_sync(gmask, td1, s);
        int   j1 = __shfl_xor_sync(gmask, ti1, s);
        float e2 = __shfl_xor_sync(gmask, td2, s);
        int   j2 = __shfl_xor_sync(gmask, ti2, s);
        ins3(e0, j0, td0, ti0, td1, ti1, td2, ti2);
        ins3(e1, j1, td0, ti0, td1, ti1, td2, ti2);
        ins3(e2, j2, td0, ti0, td1, ti1, td2, ti2);
    }

    const bool empty = !(td0 < INF);
    float r0 = (td0 < INF) ? 1.0f/(td0 + 1e-8f) : 0.0f;
    float r1 = (td1 < INF) ? 1.0f/(td1 + 1e-8f) : 0.0f;
    float r2 = (td2 < INF) ? 1.0f/(td2 + 1e-8f) : 0.0f;
    float ssum = fmaxf(r0 + r1 + r2, 1e-8f);
    float w0 = r0/ssum, w1 = r1/ssum, w2 = r2/ssum;
    if (ti0 < 0) ti0 = 0;
    if (ti1 < 0) ti1 = ti0;
    if (ti2 < 0) ti2 = ti0;

    // interp: lane handles 2 feature channels (float2) -> stage to smem
    {
        const float2* F0 = (const float2*)(g_feats + (b*NN + ti0)*32);
        const float2* F1 = (const float2*)(g_feats + (b*NN + ti1)*32);
        const float2* F2 = (const float2*)(g_feats + (b*NN + ti2)*32);
        float2 a = __ldg(&F0[l]), u = __ldg(&F1[l]), v = __ldg(&F2[l]);
        float2 f;
        f.x = empty ? 0.0f : (w0*a.x + w1*u.x + w2*v.x);
        f.y = empty ? 0.0f : (w0*a.y + w1*u.y + w2*v.y);
        ((float2*)sv[grp])[l] = f;
        if (l < 3) {
            int isel = (l == 0) ? ti0 : ((l == 1) ? ti1 : ti2);
            float4 p = __ldg(&pts[isel]);
            sv[grp][32 + l*3 + 0] = empty ? 0.0f : (cx - p.x);
            sv[grp][32 + l*3 + 1] = empty ? 0.0f : (cy - p.y);
            sv[grp][32 + l*3 + 2] = empty ? 0.0f : (cz - p.z);
        }
    }
    __syncwarp();

    // fused grouped conv: lane computes output channels 2l, 2l+1
    const float* wrow = g_wT + g*(41*CAGG) + 2*l;
    float a0 = 0.0f, a1 = 0.0f;
    #pragma unroll
    for (int i = 0; i < 41; ++i) {
        float vi = sv[grp][i];
        float2 w = *(const float2*)(wrow + i*CAGG);
        a0 = fmaf(vi, w.x, a0);
        a1 = fmaf(vi, w.y, a1);
    }
    const int gc = g*CAGG + 2*l;
    float2 r;
    r.x = fmaxf(fmaf(a0, __ldg(&g_sc1[gc]),   __ldg(&g_sh1[gc])),   0.0f);
    r.y = fmaxf(fmaf(a1, __ldg(&g_sc1[gc+1]), __ldg(&g_sh1[gc+1])), 0.0f);
    *(float2*)(g_x + m*GC + gc) = r;
}

// ---------------------------------------------------------------------------
// K_post: split-K GEMM partials. CTA tile 64m x 64n, ONE k-chunk of 32.
// block 128: nq = tid&15 (16 x 4n), mq = tid>>4 (8 x 8m). 8x4 regs.
// grid (16, 2, 27) = 864 CTAs (~6 CTAs/SM to hide the fill burst).
// ---------------------------------------------------------------------------
__global__ __launch_bounds__(128) void k_post(const float* __restrict__ wp) {
    __shared__ float sA[32][68];    // [k][m] pitch 68 (16B-aligned rows)
    __shared__ float sB[32][68];    // [k][n]
    const int tid = threadIdx.x;
    const int nq = tid & 15;
    const int mq = tid >> 4;
    const int m0 = blockIdx.x * 64;
    const int c0 = blockIdx.y * 64;
    const int kb = blockIdx.z * 32;

    // A: 64m x 32k = 512 float4; 128 threads x 4
    #pragma unroll
    for (int i = 0; i < 4; ++i) {
        int f = tid + i*128;
        int mm = f >> 3, kq = (f & 7) << 2;
        float4 vv = *(const float4*)(g_x + (m0+mm)*GC + kb + kq);
        sA[kq+0][mm] = vv.x; sA[kq+1][mm] = vv.y;
        sA[kq+2][mm] = vv.z; sA[kq+3][mm] = vv.w;
    }
    // B: 64n x 32k = 512 float4; 128 threads x 4
    #pragma unroll
    for (int i = 0; i < 4; ++i) {
        int f = tid + i*128;
        int nr = f >> 3, kq = (f & 7) << 2;
        float4 vv = *(const float4*)(wp + (c0+nr)*GC + kb + kq);
        sB[kq+0][nr] = vv.x; sB[kq+1][nr] = vv.y;
        sB[kq+2][nr] = vv.z; sB[kq+3][nr] = vv.w;
    }
    __syncthreads();

    float acc[8][4];
    #pragma unroll
    for (int i = 0; i < 8; ++i)
        #pragma unroll
        for (int j = 0; j < 4; ++j) acc[i][j] = 0.0f;

    #pragma unroll
    for (int k = 0; k < 32; ++k) {
        float av[8], bv[4];
        *(float4*)&av[0] = *(const float4*)&sA[k][mq*8];
        *(float4*)&av[4] = *(const float4*)&sA[k][mq*8 + 4];
        *(float4*)&bv[0] = *(const float4*)&sB[k][nq*4];
        #pragma unroll
        for (int i = 0; i < 8; ++i)
            #pragma unroll
            for (int j = 0; j < 4; ++j)
                acc[i][j] = fmaf(av[i], bv[j], acc[i][j]);
    }

    float* dst = g_part[blockIdx.z];
    #pragma unroll
    for (int i = 0; i < 8; ++i) {
        int mrow = m0 + mq*8 + i;
        *(float4*)(dst + mrow*CPOST + c0 + nq*4) = *(float4*)&acc[i][0];
    }
}

// ---------------------------------------------------------------------------
// K_fin: sum split-K partials + BN2 + ReLU
// ---------------------------------------------------------------------------
__global__ void k_fin(const float* __restrict__ g2, const float* __restrict__ b2,
                      const float* __restrict__ mu2, const float* __restrict__ v2,
                      float* __restrict__ out) {
    int t = blockIdx.x * 256 + threadIdx.x;
    if (t >= BM*CPOST) return;
    int c = t & 127;
    float s = 0.0f;
    #pragma unroll
    for (int k = 0; k < KSPLIT; ++k) s += g_part[k][t];
    float scale = g2[c] * rsqrtf(v2[c] + 1e-5f);
    float shift = b2[c] - mu2[c]*scale;
    out[t] = fmaxf(fmaf(s, scale, shift), 0.0f);
}

// ---------------------------------------------------------------------------
extern "C" void kernel_launch(void* const* d_in, const int* in_sizes, int n_in,
                              void* d_out, int out_size) {
    const float* sxyz  = (const float*)d_in[0];
    const float* sfeat = (const float*)d_in[1];
    const float* nxyz  = (const float*)d_in[2];
    const float* wg    = (const float*)d_in[3];
    const float* g1    = (const float*)d_in[4];
    const float* b1    = (const float*)d_in[5];
    const float* m1    = (const float*)d_in[6];
    const float* v1    = (const float*)d_in[7];
    const float* wp    = (const float*)d_in[8];
    const float* g2    = (const float*)d_in[9];
    const float* b2    = (const float*)d_in[10];
    const float* m2    = (const float*)d_in[11];
    const float* v2    = (const float*)d_in[12];
    float* out = (float*)d_out;

    const int wtBlocks = (GG*41*CAGG + 1023) / 1024;      // 35
    k_pre<<<BB + wtBlocks, 1024>>>(sxyz, wg, g1, b1, m1, v1);
    k_reduce<<<(BB*NN*8 + 255)/256, 256>>>(sfeat);
    k_nn<<<NCENT/16, 256>>>(nxyz);
    k_post<<<dim3(BM/64, CPOST/64, KSPLIT), 128>>>(wp);
    k_fin<<<(BM*CPOST + 255)/256, 256>>>(g2, b2, m2, v2, out);
}